// round 1
// baseline (speedup 1.0000x reference)
#include <cuda_runtime.h>

// ---------------------------------------------------------------------------
// VQ-VAE forward on B200 (sm_100a).  Pure fp32 direct convs, register-tiled.
//   conv  k=4 s=2 p=1  (encoder x3, ReLU on first two)
//   VQ    argmin over 512 codes of dim 64 (rows = 64 consecutive NCHW elems)
//   dconv k=4 s=2 p=1  (decoder x3, ReLU on first two)
// Output layout assumed: [x_recon | z_e | z_q | idx(as float)], fp32.
// ---------------------------------------------------------------------------

#define NBATCH 16

// -------- scratch (static device globals: allocation-free) -----------------
__device__ float g_h1[NBATCH * 128 * 128 * 128];  // conv1 out  (128 MB)
__device__ float g_h2[NBATCH * 256 * 64 * 64];    // conv2 out  ( 64 MB)
__device__ float g_g1[NBATCH * 256 * 64 * 64];    // dconv1 out ( 64 MB)
__device__ float g_g2[NBATCH * 128 * 128 * 128];  // dconv2 out (128 MB)
__device__ float g_ze[NBATCH * 64 * 32 * 32];
__device__ float g_zq[NBATCH * 64 * 32 * 32];
__device__ float g_if[16384];
__device__ float g_wt1[128 * 3 * 16];             // transposed conv weights
__device__ float g_wt2[256 * 128 * 16];
__device__ float g_wt3[64 * 256 * 16];

// -------- weight transpose: OIHW -> [ic][oc][t] ----------------------------
__global__ void wtrans(const float* __restrict__ w, float* __restrict__ wo,
                       int Cout, int Cin) {
    int idx = blockIdx.x * 256 + threadIdx.x;
    int total = Cout * Cin * 16;
    if (idx < total) {
        int t = idx & 15;
        int rest = idx >> 4;
        int ic = rest % Cin;
        int oc = rest / Cin;
        wo[(ic * Cout + oc) * 16 + t] = w[idx];
    }
}

// -------- generic conv k4 s2 p1 --------------------------------------------
// Block: 64 output channels x 16x16 spatial tile, one batch image.
// Thread: 8 oc x (1 row x 8 cols).  Weights pre-transposed to [ic][oc][t].
template <int CIN, bool RELU>
__global__ __launch_bounds__(256, 2)
void conv4s2(const float* __restrict__ in, const float* __restrict__ wt,
             const float* __restrict__ bias, float* __restrict__ out,
             int Cout, int Hin, int Win, int Hout, int Wout, int tilesX) {
    __shared__ float ish[34 * 35];            // input patch, stride 35
    __shared__ float wsh[64 * 16];            // [oc][t]

    const int tile = blockIdx.x;
    const int tx0 = (tile % tilesX) * 16;
    const int ty0 = (tile / tilesX) * 16;
    const int ocb = blockIdx.y * 64;
    const int b   = blockIdx.z;

    const int tid = threadIdx.x;
    const int og  = tid >> 5;                 // warp id -> oc group (uniform)
    const int sp  = tid & 31;
    const int r   = sp >> 1;                  // output row 0..15
    const int cb  = (sp & 1) * 8;             // col base 0 or 8

    float acc[8][8];
#pragma unroll
    for (int o = 0; o < 8; o++) {
        float bv = bias[ocb + og * 8 + o];
#pragma unroll
        for (int j = 0; j < 8; j++) acc[o][j] = bv;
    }

    const int iy0 = ty0 * 2 - 1, ix0 = tx0 * 2 - 1;
    const float* inB = in + (b * CIN) * Hin * Win;

    for (int ic = 0; ic < CIN; ic++) {
        const float* inC = inB + ic * Hin * Win;
        for (int idx = tid; idx < 34 * 34; idx += 256) {
            int py = idx / 34, px = idx - py * 34;
            int iy = iy0 + py, ix = ix0 + px;
            float v = 0.f;
            if ((unsigned)iy < (unsigned)Hin && (unsigned)ix < (unsigned)Win)
                v = inC[iy * Win + ix];
            ish[py * 35 + px] = v;
        }
        const float* wC = wt + (ic * Cout + ocb) * 16;  // contiguous 1024
        for (int idx = tid; idx < 1024; idx += 256) wsh[idx] = wC[idx];
        __syncthreads();

#pragma unroll
        for (int t = 0; t < 16; t++) {
            const int ky = t >> 2, kx = t & 3;
            float wv[8];
#pragma unroll
            for (int o = 0; o < 8; o++) wv[o] = wsh[(og * 8 + o) * 16 + t];
            float iv[8];
            const int base = (2 * r + ky) * 35 + 2 * cb + kx;
#pragma unroll
            for (int j = 0; j < 8; j++) iv[j] = ish[base + 2 * j];
#pragma unroll
            for (int o = 0; o < 8; o++)
#pragma unroll
                for (int j = 0; j < 8; j++)
                    acc[o][j] = fmaf(wv[o], iv[j], acc[o][j]);
        }
        __syncthreads();
    }

    const int oy = ty0 + r;
    const int oxb = tx0 + cb;
#pragma unroll
    for (int o = 0; o < 8; o++) {
        float* op = out + ((b * Cout + ocb + og * 8 + o) * Hout + oy) * Wout + oxb;
        float tmp[8];
#pragma unroll
        for (int j = 0; j < 8; j++)
            tmp[j] = RELU ? fmaxf(acc[o][j], 0.f) : acc[o][j];
        *(float4*)op       = make_float4(tmp[0], tmp[1], tmp[2], tmp[3]);
        *(float4*)(op + 4) = make_float4(tmp[4], tmp[5], tmp[6], tmp[7]);
    }
}

// -------- generic transposed conv k4 s2 p1 (gather form) -------------------
// out[oy,ox] = sum_{ic,ky,kx valid} in[ic,(oy+1-ky)/2,(ox+1-kx)/2] * w[ic,oc,ky,kx]
// Per output parity exactly 2x2 taps.  Block: 64 oc x 16x16 out tile.
// Thread: 8 oc x 8 cols of one quadrant row (fixed parity -> fixed taps).
template <bool RELU>
__global__ __launch_bounds__(256, 2)
void dconv4s2(const float* __restrict__ in, const float* __restrict__ wt,
              const float* __restrict__ bias, float* __restrict__ out,
              int Cin, int Cout, int Hin, int Win, int tilesX) {
    const int Hout = Hin * 2, Wout = Win * 2;
    __shared__ float wsh[4][64 * 16];          // [icc][oc][t]
    __shared__ float ish[4][10 * 13];          // [icc][10 rows x 10 cols], stride 13

    const int tile = blockIdx.x;
    const int ox0 = (tile % tilesX) * 16;
    const int oy0 = (tile / tilesX) * 16;
    const int ocb = blockIdx.y * 64;
    const int b   = blockIdx.z;

    const int tid = threadIdx.x;
    const int og  = tid >> 5;
    const int sp  = tid & 31;
    const int q   = sp >> 3;
    const int py  = q >> 1, px = q & 1;
    const int ry  = sp & 7;

    float acc[8][8];
#pragma unroll
    for (int o = 0; o < 8; o++) {
        float bv = bias[ocb + og * 8 + o];
#pragma unroll
        for (int j = 0; j < 8; j++) acc[o][j] = bv;
    }

    const int iy0 = oy0 >> 1, ix0 = ox0 >> 1;
    const int kp = 1 - py;   // ky parity base
    const int kq = 1 - px;   // kx parity base

    for (int ic0 = 0; ic0 < Cin; ic0 += 4) {
        for (int idx = tid; idx < 4 * 100; idx += 256) {
            int icc = idx / 100, p = idx - icc * 100;
            int piy = p / 10, pix = p - piy * 10;
            int iy = iy0 - 1 + piy, ix = ix0 - 1 + pix;
            float v = 0.f;
            if ((unsigned)iy < (unsigned)Hin && (unsigned)ix < (unsigned)Win)
                v = in[((b * Cin + ic0 + icc) * Hin + iy) * Win + ix];
            ish[icc][piy * 13 + pix] = v;
        }
        for (int idx = tid; idx < 4 * 1024; idx += 256) {
            int icc = idx >> 10, rmd = idx & 1023;  // rmd = oc*16+t
            wsh[icc][rmd] = wt[((ic0 + icc) * Cout + ocb) * 16 + rmd];
        }
        __syncthreads();

#pragma unroll
        for (int icc = 0; icc < 4; icc++) {
#pragma unroll
            for (int a = 0; a < 2; a++) {
                const int ky  = kp + 2 * a;
                const int liy = ry + 1 + py - a;
#pragma unroll
                for (int c = 0; c < 2; c++) {
                    const int kx = kq + 2 * c;
                    const int cc = px - c + 1;
                    const int t  = ky * 4 + kx;
                    float wv[8];
#pragma unroll
                    for (int o = 0; o < 8; o++)
                        wv[o] = wsh[icc][(og * 8 + o) * 16 + t];
                    float iv[8];
#pragma unroll
                    for (int j = 0; j < 8; j++)
                        iv[j] = ish[icc][liy * 13 + cc + j];
#pragma unroll
                    for (int o = 0; o < 8; o++)
#pragma unroll
                        for (int j = 0; j < 8; j++)
                            acc[o][j] = fmaf(wv[o], iv[j], acc[o][j]);
                }
            }
        }
        __syncthreads();
    }

    const int oy = oy0 + 2 * ry + py;
#pragma unroll
    for (int o = 0; o < 8; o++) {
        float* op = out + ((b * Cout + ocb + og * 8 + o) * Hout + oy) * Wout + ox0 + px;
#pragma unroll
        for (int j = 0; j < 8; j++) {
            float v = acc[o][j];
            if (RELU) v = fmaxf(v, 0.f);
            op[2 * j] = v;
        }
    }
}

// -------- final transposed conv: Cin=128 -> Cout=3, 128x128 -> 256x256 -----
__global__ __launch_bounds__(128, 4)
void dconv3out(const float* __restrict__ in, const float* __restrict__ wt,
               const float* __restrict__ bias, float* __restrict__ out,
               int tilesX) {
    const int Cin = 128, Hin = 128, Win = 128, Hout = 256, Wout = 256;
    __shared__ float ish[4][18 * 19];    // 18x18 patch, stride 19
    __shared__ float wsh[4][3 * 16];     // [icc][oc][t]

    const int tile = blockIdx.x;
    const int ox0 = (tile % tilesX) * 32;
    const int oy0 = (tile / tilesX) * 32;
    const int b   = blockIdx.y;

    const int tid = threadIdx.x;
    const int q   = tid >> 5;
    const int py  = q >> 1, px = q & 1;
    const int sp  = tid & 31;
    const int ry  = sp >> 1;            // 0..15 quadrant row
    const int ch  = (sp & 1) * 8;       // col base inside quadrant

    float acc[3][8];
#pragma unroll
    for (int o = 0; o < 3; o++) {
        float bv = bias[o];
#pragma unroll
        for (int j = 0; j < 8; j++) acc[o][j] = bv;
    }

    const int iy0 = oy0 >> 1, ix0 = ox0 >> 1;
    const int kp = 1 - py, kq = 1 - px;

    for (int ic0 = 0; ic0 < Cin; ic0 += 4) {
        for (int idx = tid; idx < 4 * 324; idx += 128) {
            int icc = idx / 324, p = idx - icc * 324;
            int piy = p / 18, pix = p - piy * 18;
            int iy = iy0 - 1 + piy, ix = ix0 - 1 + pix;
            float v = 0.f;
            if ((unsigned)iy < (unsigned)Hin && (unsigned)ix < (unsigned)Win)
                v = in[((b * Cin + ic0 + icc) * Hin + iy) * Win + ix];
            ish[icc][piy * 19 + pix] = v;
        }
        for (int idx = tid; idx < 4 * 48; idx += 128) {
            int icc = idx / 48, rmd = idx - icc * 48;  // oc*16+t
            wsh[icc][rmd] = wt[(ic0 + icc) * 48 + rmd];
        }
        __syncthreads();

#pragma unroll
        for (int icc = 0; icc < 4; icc++) {
#pragma unroll
            for (int a = 0; a < 2; a++) {
                const int ky  = kp + 2 * a;
                const int liy = ry + 1 + py - a;
                float iv[10];                           // covers both kx taps
                const int base = liy * 19 + ch + px;
#pragma unroll
                for (int j = 0; j < 10; j++) iv[j] = ish[icc][base + j];
#pragma unroll
                for (int c = 0; c < 2; c++) {
                    const int kx  = kq + 2 * c;
                    const int t   = ky * 4 + kx;
                    const int off = 1 - c;
                    float wv[3];
#pragma unroll
                    for (int o = 0; o < 3; o++) wv[o] = wsh[icc][o * 16 + t];
#pragma unroll
                    for (int o = 0; o < 3; o++)
#pragma unroll
                        for (int j = 0; j < 8; j++)
                            acc[o][j] = fmaf(wv[o], iv[j + off], acc[o][j]);
                }
            }
        }
        __syncthreads();
    }

    const int oy = oy0 + 2 * ry + py;
#pragma unroll
    for (int o = 0; o < 3; o++) {
        float* op = out + ((b * 3 + o) * Hout + oy) * Wout + ox0 + px + 2 * ch;
#pragma unroll
        for (int j = 0; j < 8; j++) op[2 * j] = acc[o][j];
    }
}

// -------- vector quantize ---------------------------------------------------
// 16384 rows (64 consecutive fp32 each) vs 512 codes.  One thread per row.
__global__ __launch_bounds__(128, 8)
void vqk(const float* __restrict__ ze, const float* __restrict__ emb,
         float* __restrict__ zq, float* __restrict__ idxf) {
    __shared__ __align__(16) float esh[64 * 64];
    __shared__ float en[64];

    const int row = blockIdx.x * 128 + threadIdx.x;
    float f[64];
    const float4* fp = (const float4*)(ze + row * 64);
#pragma unroll
    for (int i = 0; i < 16; i++) {
        float4 v = fp[i];
        f[4 * i] = v.x; f[4 * i + 1] = v.y; f[4 * i + 2] = v.z; f[4 * i + 3] = v.w;
    }
    float fn = 0.f;
#pragma unroll
    for (int d = 0; d < 64; d++) fn = fmaf(f[d], f[d], fn);

    float best = 3.4e38f;
    int bidx = 0;
    for (int cb = 0; cb < 512; cb += 64) {
        __syncthreads();
        const float4* src = (const float4*)(emb + cb * 64);
        for (int i = threadIdx.x; i < 1024; i += 128)
            ((float4*)esh)[i] = src[i];
        __syncthreads();
        if (threadIdx.x < 64) {
            float s = 0.f;
            const float* e = esh + threadIdx.x * 64;
#pragma unroll
            for (int d = 0; d < 64; d++) s = fmaf(e[d], e[d], s);
            en[threadIdx.x] = s;
        }
        __syncthreads();
        for (int c = 0; c < 64; c++) {
            const float4* ev = (const float4*)(esh + c * 64);
            float dot = 0.f;
#pragma unroll
            for (int i = 0; i < 16; i++) {
                float4 e = ev[i];
                dot = fmaf(f[4 * i], e.x, dot);
                dot = fmaf(f[4 * i + 1], e.y, dot);
                dot = fmaf(f[4 * i + 2], e.z, dot);
                dot = fmaf(f[4 * i + 3], e.w, dot);
            }
            float sc = fn - 2.f * dot + en[c];
            if (sc < best) { best = sc; bidx = cb + c; }
        }
    }

    idxf[row] = (float)bidx;
    const float4* ep = (const float4*)(emb + bidx * 64);
    float4* qp = (float4*)(zq + row * 64);
#pragma unroll
    for (int i = 0; i < 16; i++) qp[i] = ep[i];
}

// ---------------------------------------------------------------------------
extern "C" void kernel_launch(void* const* d_in, const int* in_sizes, int n_in,
                              void* d_out, int out_size) {
    (void)in_sizes; (void)n_in;
    const float* x   = (const float*)d_in[0];
    const float* w1  = (const float*)d_in[1];
    const float* b1  = (const float*)d_in[2];
    const float* w2  = (const float*)d_in[3];
    const float* b2  = (const float*)d_in[4];
    const float* w3  = (const float*)d_in[5];
    const float* b3  = (const float*)d_in[6];
    const float* d1w = (const float*)d_in[7];
    const float* d1b = (const float*)d_in[8];
    const float* d2w = (const float*)d_in[9];
    const float* d2b = (const float*)d_in[10];
    const float* d3w = (const float*)d_in[11];
    const float* d3b = (const float*)d_in[12];
    const float* emb = (const float*)d_in[13];

    float *h1, *h2, *g1, *g2, *ze, *zq, *idxf, *wt1, *wt2, *wt3;
    cudaGetSymbolAddress((void**)&h1, g_h1);
    cudaGetSymbolAddress((void**)&h2, g_h2);
    cudaGetSymbolAddress((void**)&g1, g_g1);
    cudaGetSymbolAddress((void**)&g2, g_g2);
    cudaGetSymbolAddress((void**)&ze, g_ze);
    cudaGetSymbolAddress((void**)&zq, g_zq);
    cudaGetSymbolAddress((void**)&idxf, g_if);
    cudaGetSymbolAddress((void**)&wt1, g_wt1);
    cudaGetSymbolAddress((void**)&wt2, g_wt2);
    cudaGetSymbolAddress((void**)&wt3, g_wt3);

    float* outF = (float*)d_out;
    const int NX = NBATCH * 3 * 256 * 256;   // 3145728
    const int NZ = NBATCH * 64 * 32 * 32;    // 1048576
    const int NI = 16384;
    if (out_size >= NX + 2 * NZ + NI) {      // full tuple layout
        ze   = outF + NX;
        zq   = outF + NX + NZ;
        idxf = outF + NX + 2 * NZ;
    }

    // weight transposes (tiny)
    wtrans<<<(128 * 3 * 16 + 255) / 256, 256>>>(w1, wt1, 128, 3);
    wtrans<<<(256 * 128 * 16 + 255) / 256, 256>>>(w2, wt2, 256, 128);
    wtrans<<<(64 * 256 * 16 + 255) / 256, 256>>>(w3, wt3, 64, 256);

    // encoder
    conv4s2<3, true><<<dim3(64, 2, NBATCH), 256>>>(x, wt1, b1, h1, 128, 256, 256, 128, 128, 8);
    conv4s2<128, true><<<dim3(16, 4, NBATCH), 256>>>(h1, wt2, b2, h2, 256, 128, 128, 64, 64, 4);
    conv4s2<256, false><<<dim3(4, 1, NBATCH), 256>>>(h2, wt3, b3, ze, 64, 64, 64, 32, 32, 2);

    // quantize
    vqk<<<128, 128>>>(ze, emb, zq, idxf);

    // decoder
    dconv4s2<true><<<dim3(16, 4, NBATCH), 256>>>(zq, d1w, d1b, g1, 64, 256, 32, 32, 4);
    dconv4s2<true><<<dim3(64, 2, NBATCH), 256>>>(g1, d2w, d2b, g2, 256, 128, 64, 64, 8);
    dconv3out<<<dim3(64, NBATCH), 128>>>(g2, d3w, d3b, outF, 8);
}